// round 10
// baseline (speedup 1.0000x reference)
#include <cuda_runtime.h>
#include <cstdint>

// LSTM(B=8192, T=1024, H=10, in=1) -> final cell state c_T -> Linear(10,1).
//
// R9 = R8 math + 4-warp blocks + software-pipelined h-table reads.
//  * Duplicated-h smem table; gate-PAIR f32x2 accumulation (22 ffma2/step):
//    acc_if=(pre_i,pre_f), acc_go=(pre_g,pre_o); zero horizontal adds.
//  * PREFETCH: step t's 5 LDS.128 issue at the END of step t-1, right after
//    the STS that completes that table (intra-warp lockstep => all lanes'
//    stores precede program-order-later loads; no syncwarp needed).
//    This removes the 29-cyc LDS latency from the per-step serial chain.
//  * 4-warp blocks (683): the block shape that measured issue=0.475 in
//    R5/R7, vs 0.406 with R8's 1-warp blocks. launch_bounds(128,5) keeps
//    regs<=102 so 5 blocks/SM fit (no second-wave tail).
//
// Math: tanh.approx everywhere; sigma(x)=0.5+0.5*tanh(x/2) folded into
// pre-scaled weights; state h'=2h folded into W_hh; x via hoisted (x,x).

#define B_TOT 8192
#define T_LEN 1024
#define HID   10
#define GPW   3                  // batches per warp
#define WPB   4                  // warps per block
#define THREADS (WPB * 32)
#define BATCH_PER_BLOCK (WPB * GPW)   // 12
#define GSTRIDE 24               // floats per group region

typedef unsigned long long ull;

__device__ __forceinline__ ull pack2(float x, float y) {
    ull r;
    asm("mov.b64 %0, {%1, %2};" : "=l"(r) : "f"(x), "f"(y));
    return r;
}
__device__ __forceinline__ void unpack2(ull v, float& x, float& y) {
    asm("mov.b64 {%0, %1}, %2;" : "=f"(x), "=f"(y) : "l"(v));
}
__device__ __forceinline__ ull ffma2(ull a, ull b, ull c) {
    ull d;
    asm("fma.rn.f32x2 %0, %1, %2, %3;" : "=l"(d) : "l"(a), "l"(b), "l"(c));
    return d;
}
__device__ __forceinline__ float ftanh(float x) {
    float r;
    asm("tanh.approx.f32 %0, %1;" : "=f"(r) : "f"(x));
    return r;
}
__device__ __forceinline__ void lds_v2b64(uint32_t addr, ull& a, ull& b) {
    asm volatile("ld.shared.v2.b64 {%0, %1}, [%2];" : "=l"(a), "=l"(b) : "r"(addr));
}
__device__ __forceinline__ void sts_dup(uint32_t addr, float v) {
    asm volatile("st.shared.v2.f32 [%0], {%1, %1};" :: "r"(addr), "f"(v) : "memory");
}
__device__ __forceinline__ uint32_t smem_u32(const void* p) {
    uint32_t a;
    asm("{ .reg .u64 t; cvta.to.shared.u64 t, %1; cvt.u32.u64 %0, t; }"
        : "=r"(a) : "l"(p));
    return a;
}

__global__ __launch_bounds__(THREADS, 5)
void lstm_lin_kernel(const float* __restrict__ x,       // [B, T, 1]
                     const float* __restrict__ W_ih,    // [4H, 1]
                     const float* __restrict__ W_hh,    // [4H, H]
                     const float* __restrict__ b_ih,    // [4H]
                     const float* __restrict__ b_hh,    // [4H]
                     const float* __restrict__ W_lin,   // [1, H]
                     const float* __restrict__ b_lin,   // [1]
                     float* __restrict__ out)           // [B, 1]
{
    // [parity][warp][group][24 floats]; dup h-pairs at floats 2r,2r+1.
    __shared__ float hbuf[2][WPB][GPW][GSTRIDE];

    const int warp  = threadIdx.x >> 5;
    const int wlane = threadIdx.x & 31;
    const int group = wlane / HID;          // 0..2 active; 3 => lanes 30,31
    const int r     = wlane - group * HID;  // unit 0..9
    const int base  = group * HID;
    const bool active = (group < GPW);
    const int sgrp   = active ? group : 0;

    const int gbatch = (blockIdx.x * WPB + warp) * GPW + group;
    const bool valid = active && (gbatch < B_TOT);
    const int b = valid ? gbatch : 0;

    // ---- per-lane weights, GATE-paired & pre-scaled ----
    ull wif[HID], wgo[HID];
#pragma unroll
    for (int k = 0; k < HID; k++) {
        wif[k] = pack2(W_hh[(0 * HID + r) * HID + k] * 0.25f,
                       W_hh[(1 * HID + r) * HID + k] * 0.25f);
        wgo[k] = pack2(W_hh[(2 * HID + r) * HID + k] * 0.50f,
                       W_hh[(3 * HID + r) * HID + k] * 0.25f);
    }
    const ull wxif = pack2(W_ih[0 * HID + r] * 0.5f, W_ih[1 * HID + r] * 0.5f);
    const ull wxgo = pack2(W_ih[2 * HID + r] * 1.0f, W_ih[3 * HID + r] * 0.5f);
    const ull bif  = pack2((b_ih[0 * HID + r] + b_hh[0 * HID + r]) * 0.5f,
                           (b_ih[1 * HID + r] + b_hh[1 * HID + r]) * 0.5f);
    const ull bgo  = pack2((b_ih[2 * HID + r] + b_hh[2 * HID + r]) * 1.0f,
                           (b_ih[3 * HID + r] + b_hh[3 * HID + r]) * 0.5f);

    float c = 0.0f;

    const uint32_t smem0 = smem_u32(&hbuf[0][0][0][0]);
    const uint32_t grp_base0 = smem0 + (uint32_t)(warp * GPW + sgrp) * (GSTRIDE * 4);
    const uint32_t grp_base1 = grp_base0 + WPB * GPW * GSTRIDE * 4;   // parity-1 plane
    const uint32_t slot0 = grp_base0 + r * 8;
    const uint32_t slot1 = grp_base1 + r * 8;

    if (active) sts_dup(slot0, 0.0f);
    __syncwarp();

    const float4* __restrict__ xrow =
        reinterpret_cast<const float4*>(x + (size_t)b * T_LEN);

    // prefetch h(0) from parity-0 plane
    ull hd[HID];
    lds_v2b64(grp_base0 +  0, hd[0], hd[1]);
    lds_v2b64(grp_base0 + 16, hd[2], hd[3]);
    lds_v2b64(grp_base0 + 32, hd[4], hd[5]);
    lds_v2b64(grp_base0 + 48, hd[6], hd[7]);
    lds_v2b64(grp_base0 + 64, hd[8], hd[9]);

    for (int t4 = 0; t4 < T_LEN / 4; t4++) {
        const float4 xq = __ldg(&xrow[t4]);
        ull xx[4];
        xx[0] = pack2(xq.x, xq.x);
        xx[1] = pack2(xq.y, xq.y);
        xx[2] = pack2(xq.z, xq.z);
        xx[3] = pack2(xq.w, xq.w);

#pragma unroll
        for (int jt = 0; jt < 4; jt++) {
            // step s = t4*4+jt reads parity jt&1 (already in hd),
            // writes parity (jt&1)^1, then prefetches next step's table.
            const uint32_t wr      = (jt & 1) ? slot0 : slot1;
            const uint32_t nextrd  = (jt & 1) ? grp_base0 : grp_base1;

            ull acc_if = ffma2(xx[jt], wxif, bif);
            ull acc_go = ffma2(xx[jt], wxgo, bgo);
#pragma unroll
            for (int k = 0; k < HID; k++) {
                acc_if = ffma2(wif[k], hd[k], acc_if);
                acc_go = ffma2(wgo[k], hd[k], acc_go);
            }

            float pi, pf, pg, po;
            unpack2(acc_if, pi, pf);
            unpack2(acc_go, pg, po);
            const float ti = ftanh(pi);
            const float tf = ftanh(pf);
            const float tg = ftanh(pg);
            const float to = ftanh(po);

            // c = sigma_f*c + sigma_i*tanh_g ; sigma = 0.5 + 0.5*t
            const float sf = fmaf(0.5f, tf, 0.5f);
            const float si = fmaf(0.5f, ti, 0.5f);
            c = fmaf(sf, c, si * tg);

            // h' = 2h = (1 + tanh_o) * tanh(c); store duplicated
            const float tc = ftanh(c);
            const float hn = fmaf(to, tc, tc);
            if (active) sts_dup(wr, hn);

            asm volatile("" ::: "memory");   // pin STS before the prefetch LDS

            // prefetch next step's h-table (this warp's STS above is the
            // last write; intra-warp lockstep makes all lanes' stores
            // visible to these program-order-later loads)
            lds_v2b64(nextrd +  0, hd[0], hd[1]);
            lds_v2b64(nextrd + 16, hd[2], hd[3]);
            lds_v2b64(nextrd + 32, hd[4], hd[5]);
            lds_v2b64(nextrd + 48, hd[6], hd[7]);
            lds_v2b64(nextrd + 64, hd[8], hd[9]);
        }
    }

    // ---- epilogue: out[b] = sum_u c[u] * W_lin[u] + b_lin ----
    float part = c * W_lin[r];
    float sum = part;
#pragma unroll
    for (int j = 1; j < HID; j++)
        sum += __shfl_sync(0xffffffffu, part, base + j);

    if (valid && r == 0) {
        out[gbatch] = sum + b_lin[0];
    }
}

extern "C" void kernel_launch(void* const* d_in, const int* in_sizes, int n_in,
                              void* d_out, int out_size) {
    const float* x     = (const float*)d_in[0];
    const float* W_ih  = (const float*)d_in[1];
    const float* W_hh  = (const float*)d_in[2];
    const float* b_ih  = (const float*)d_in[3];
    const float* b_hh  = (const float*)d_in[4];
    const float* W_lin = (const float*)d_in[5];
    const float* b_lin = (const float*)d_in[6];
    float* out = (float*)d_out;

    const int blocks = (B_TOT + BATCH_PER_BLOCK - 1) / BATCH_PER_BLOCK;  // 683
    lstm_lin_kernel<<<blocks, THREADS>>>(
        x, W_ih, W_hh, b_ih, b_hh, W_lin, b_lin, out);
}